// round 3
// baseline (speedup 1.0000x reference)
#include <cuda_runtime.h>

// Problem constants (match reference)
#define BATCH      32768
#define NFEAT      128
#define NTREES     4000
#define NINT       63
#define NLEAF      64
#define NCLS       10
#define TREE_DEPTH 6
#define LR         0.1f

// Tiling
#define TPB          128   // threads per CTA = samples per CTA
#define CHUNK_STAGES 4
#define CHUNK_TREES  (CHUNK_STAGES * NCLS)   // 40 trees per smem chunk
#define XSTRIDE      132   // padded x row stride (floats) to decorrelate banks

// Shared memory layout (dynamic):
//   xs     : TPB * XSTRIDE floats            = 67584 B
//   nodes  : CHUNK_TREES * 64 int2 (f,thr)   = 20480 B
//   leaves : CHUNK_TREES * 64 floats         = 10240 B
#define SMEM_XS_BYTES    (TPB * XSTRIDE * 4)
#define SMEM_NODE_BYTES  (CHUNK_TREES * 64 * 8)
#define SMEM_LEAF_BYTES  (CHUNK_TREES * 64 * 4)
#define SMEM_TOTAL       (SMEM_XS_BYTES + SMEM_NODE_BYTES + SMEM_LEAF_BYTES)

extern __shared__ char smem_raw[];

__global__ void __launch_bounds__(TPB, 2)
gbt_forest_kernel(const float* __restrict__ x,
                  const int*   __restrict__ features,
                  const float* __restrict__ thresholds,
                  const float* __restrict__ leaf_values,
                  const float* __restrict__ init_out,
                  float*       __restrict__ out)
{
    float* xs     = reinterpret_cast<float*>(smem_raw);
    int2*  nodes  = reinterpret_cast<int2*>(smem_raw + SMEM_XS_BYTES);
    float* leaves = reinterpret_cast<float*>(smem_raw + SMEM_XS_BYTES + SMEM_NODE_BYTES);

    const int tid        = threadIdx.x;
    const int sampleBase = blockIdx.x * TPB;

    // ---- Load x tile: 128 samples x 128 features, coalesced float4 ----
    {
        const float4* xg = reinterpret_cast<const float4*>(x + (size_t)sampleBase * NFEAT);
        #pragma unroll
        for (int i = tid; i < TPB * (NFEAT / 4); i += TPB) {
            int row = i >> 5;      // NFEAT/4 = 32 float4 per row
            int c4  = i & 31;
            float4 v = xg[i];
            *reinterpret_cast<float4*>(xs + row * XSTRIDE + c4 * 4) = v;
        }
    }

    float acc[NCLS];
    #pragma unroll
    for (int k = 0; k < NCLS; k++) acc[k] = 0.0f;

    const float* xrow = xs + tid * XSTRIDE;

    // ---- Loop over tree chunks: stage 40 trees in smem, traverse ----
    for (int chunk = 0; chunk < NTREES / CHUNK_TREES; chunk++) {
        const int treeBase = chunk * CHUNK_TREES;

        __syncthreads();   // previous chunk's traversals done before overwrite
        for (int i = tid; i < CHUNK_TREES * 64; i += TPB) {
            int t = i >> 6;
            int n = i & 63;
            int2 nd;
            if (n < NINT) {
                nd.x = features  [(size_t)(treeBase + t) * NINT + n];
                nd.y = __float_as_int(thresholds[(size_t)(treeBase + t) * NINT + n]);
            } else {
                nd.x = 0; nd.y = 0;   // pad slot 63
            }
            nodes[i]  = nd;
            leaves[i] = leaf_values[(size_t)(treeBase + t) * NLEAF + n];
        }
        __syncthreads();

        // 4 stages x 10 class-trees; the k-unroll gives 10 independent
        // traversal chains per thread (MLP for the LDS pipe) and makes
        // acc[k] a compile-time register index.
        for (int sg = 0; sg < CHUNK_STAGES; sg++) {
            #pragma unroll
            for (int k = 0; k < NCLS; k++) {
                const int2* nt = nodes + (sg * NCLS + k) * 64;
                int idx = 0;
                #pragma unroll
                for (int l = 0; l < TREE_DEPTH; l++) {
                    int2  nd  = nt[idx];
                    float thr = __int_as_float(nd.y);
                    float xv  = xrow[nd.x];
                    idx = 2 * idx + 1 + (xv > thr ? 1 : 0);
                }
                acc[k] += leaves[(sg * NCLS + k) * 64 + (idx - NINT)];
            }
        }
    }

    // ---- Epilogue: out = init_out + LR * sum ----
    const int sample = sampleBase + tid;
    #pragma unroll
    for (int k = 0; k < NCLS; k++) {
        out[(size_t)sample * NCLS + k] = __ldg(init_out + k) + LR * acc[k];
    }
}

extern "C" void kernel_launch(void* const* d_in, const int* in_sizes, int n_in,
                              void* d_out, int out_size)
{
    (void)in_sizes; (void)n_in; (void)out_size;

    const float* x           = (const float*)d_in[0];
    const int*   features    = (const int*)  d_in[1];
    const float* thresholds  = (const float*)d_in[2];
    const float* leaf_values = (const float*)d_in[3];
    const float* init_out    = (const float*)d_in[4];
    float*       out         = (float*)d_out;

    static bool attr_set = false;
    if (!attr_set) {
        cudaFuncSetAttribute(gbt_forest_kernel,
                             cudaFuncAttributeMaxDynamicSharedMemorySize,
                             SMEM_TOTAL);
        attr_set = true;
    }

    gbt_forest_kernel<<<BATCH / TPB, TPB, SMEM_TOTAL>>>(
        x, features, thresholds, leaf_values, init_out, out);
}

// round 4
// speedup vs baseline: 1.7341x; 1.7341x over previous
#include <cuda_runtime.h>
#include <cstdint>

// Problem constants
#define BATCH      32768
#define NFEAT      128
#define NTREES     4000
#define NINT       63
#define NLEAF      64
#define NCLS       10
#define TREE_DEPTH 6
#define LR         0.1f

// Tiling: one CTA per SM, balanced grid
#define TPB        224                      // 7 warps = 224 samples per CTA
#define GRID       ((BATCH + TPB - 1) / TPB)  // 147 CTAs over 148 SMs
#define XSTRIDE    129                      // ODD stride: same-feature gather is bank-conflict-free

#define CHUNK_STAGES 4
#define CHUNK_TREES  (CHUNK_STAGES * NCLS)  // 40 trees per buffer
#define NCHUNK       (NTREES / CHUNK_TREES) // 100

#define FEAT_WORDS  (CHUNK_TREES * NINT)    // 2520
#define LEAF_WORDS  (CHUNK_TREES * NLEAF)   // 2560
#define FEAT_BYTES  (FEAT_WORDS * 4)        // 10080 (16B multiple)
#define LEAF_BYTES  (LEAF_WORDS * 4)        // 10240 (16B multiple)
#define BUF_BYTES   (2 * FEAT_BYTES + LEAF_BYTES)  // 30400 per buffer
#define XS_BYTES    (TPB * XSTRIDE * 4)     // 115584 (16B multiple)
#define MBAR_OFF    (XS_BYTES + 2 * BUF_BYTES)     // 176384 (8B aligned)
#define SMEM_TOTAL  (MBAR_OFF + 16)

extern __shared__ char smem_raw[];

__device__ __forceinline__ uint32_t s2u(const void* p) {
    uint32_t a;
    asm("{ .reg .u64 t; cvta.to.shared.u64 t, %1; cvt.u32.u64 %0, t; }"
        : "=r"(a) : "l"(p));
    return a;
}

__device__ __forceinline__ void mbar_init(uint32_t bar, uint32_t cnt) {
    asm volatile("mbarrier.init.shared.b64 [%0], %1;" :: "r"(bar), "r"(cnt) : "memory");
}

__device__ __forceinline__ void mbar_expect_tx(uint32_t bar, uint32_t bytes) {
    asm volatile("mbarrier.arrive.expect_tx.shared.b64 _, [%0], %1;"
                 :: "r"(bar), "r"(bytes) : "memory");
}

__device__ __forceinline__ void mbar_wait(uint32_t bar, uint32_t parity) {
    uint32_t done;
    asm volatile(
        "{\n\t.reg .pred p;\n\t"
        "mbarrier.try_wait.parity.acquire.cta.shared::cta.b64 p, [%1], %2;\n\t"
        "selp.b32 %0, 1, 0, p;\n\t}"
        : "=r"(done) : "r"(bar), "r"(parity) : "memory");
    while (!done) {
        asm volatile(
            "{\n\t.reg .pred p;\n\t"
            "mbarrier.try_wait.parity.acquire.cta.shared::cta.b64 p, [%1], %2, 0x989680;\n\t"
            "selp.b32 %0, 1, 0, p;\n\t}"
            : "=r"(done) : "r"(bar), "r"(parity) : "memory");
    }
}

__device__ __forceinline__ void bulk_g2s(uint32_t dst, const void* src,
                                         uint32_t bytes, uint32_t bar) {
    asm volatile(
        "cp.async.bulk.shared::cluster.global.mbarrier::complete_tx::bytes "
        "[%0], [%1], %2, [%3];"
        :: "r"(dst), "l"(src), "r"(bytes), "r"(bar) : "memory");
}

__global__ void __launch_bounds__(TPB, 1)
gbt_forest_kernel(const float* __restrict__ x,
                  const int*   __restrict__ features,
                  const float* __restrict__ thresholds,
                  const float* __restrict__ leaf_values,
                  const float* __restrict__ init_out,
                  float*       __restrict__ out)
{
    float* xs = reinterpret_cast<float*>(smem_raw);

    // Per-buffer views: [feat 63-stride ints][thr 63-stride floats][leaves 64-stride]
    char* buf0 = smem_raw + XS_BYTES;
    char* buf1 = buf0 + BUF_BYTES;
    uint64_t* mbar = reinterpret_cast<uint64_t*>(smem_raw + MBAR_OFF);

    const int tid  = threadIdx.x;
    const int base = blockIdx.x * TPB;
    const int rows = min(TPB, BATCH - base);

    const uint32_t bar0 = s2u(&mbar[0]);
    const uint32_t bar1 = s2u(&mbar[1]);
    const uint32_t dst0 = s2u(buf0);
    const uint32_t dst1 = s2u(buf1);

    // --- init barriers + prefetch chunks 0 and 1 via bulk-async (no l1tex cost) ---
    if (tid == 0) {
        mbar_init(bar0, 1);
        mbar_init(bar1, 1);
        asm volatile("fence.proxy.async.shared::cta;" ::: "memory");
        mbar_expect_tx(bar0, BUF_BYTES);
        bulk_g2s(dst0,                  features,                 FEAT_BYTES, bar0);
        bulk_g2s(dst0 + FEAT_BYTES,     thresholds,               FEAT_BYTES, bar0);
        bulk_g2s(dst0 + 2 * FEAT_BYTES, leaf_values,              LEAF_BYTES, bar0);
        mbar_expect_tx(bar1, BUF_BYTES);
        bulk_g2s(dst1,                  features   + FEAT_WORDS,  FEAT_BYTES, bar1);
        bulk_g2s(dst1 + FEAT_BYTES,     thresholds + FEAT_WORDS,  FEAT_BYTES, bar1);
        bulk_g2s(dst1 + 2 * FEAT_BYTES, leaf_values + LEAF_WORDS, LEAF_BYTES, bar1);
    }

    // --- stage x tile (overlaps with TMA): coalesced loads, conflict-free STS ---
    for (int i = tid; i < rows * NFEAT; i += TPB) {
        xs[(i >> 7) * XSTRIDE + (i & (NFEAT - 1))] = x[(size_t)base * NFEAT + i];
    }
    __syncthreads();   // orders mbar_init before any other thread's wait

    float acc[NCLS];
    #pragma unroll
    for (int k = 0; k < NCLS; k++) acc[k] = 0.0f;

    const float* xrow = xs + tid * XSTRIDE;

    // Ping-pong state (kept in registers via explicit swap, no indexed arrays)
    uint32_t barCur = bar0, barNxt = bar1;
    uint32_t dstCur = dst0, dstNxt = dst1;
    const char* pCur = buf0;
    const char* pNxt = buf1;
    int phCur = 0, phNxt = 0;

    for (int c = 0; c < NCHUNK; c++) {
        mbar_wait(barCur, phCur);
        phCur ^= 1;

        const int*   featB = reinterpret_cast<const int*>(pCur);
        const float* thrB  = reinterpret_cast<const float*>(pCur + FEAT_BYTES);
        const float* leafB = reinterpret_cast<const float*>(pCur + 2 * FEAT_BYTES);

        for (int sg = 0; sg < CHUNK_STAGES; sg++) {
            #pragma unroll
            for (int k = 0; k < NCLS; k++) {
                const int j = sg * NCLS + k;
                const int*   ft = featB + j * NINT;
                const float* tt = thrB  + j * NINT;
                int idx = 0;
                #pragma unroll
                for (int l = 0; l < TREE_DEPTH; l++) {
                    int   f   = ft[idx];          // conflict-free (consecutive range mod 32)
                    float thr = tt[idx];          // conflict-free
                    idx = 2 * idx + 1 + (xrow[f] > thr);
                }
                acc[k] += leafB[j * NLEAF + (idx - NINT)];
            }
        }

        __syncthreads();   // all warps done with this buffer before overwrite
        if (c + 2 < NCHUNK && tid == 0) {
            const int nc = c + 2;
            mbar_expect_tx(barCur, BUF_BYTES);
            bulk_g2s(dstCur,                  features    + (size_t)nc * FEAT_WORDS, FEAT_BYTES, barCur);
            bulk_g2s(dstCur + FEAT_BYTES,     thresholds  + (size_t)nc * FEAT_WORDS, FEAT_BYTES, barCur);
            bulk_g2s(dstCur + 2 * FEAT_BYTES, leaf_values + (size_t)nc * LEAF_WORDS, LEAF_BYTES, barCur);
        }

        // swap cur/nxt
        uint32_t tb = barCur; barCur = barNxt; barNxt = tb;
        uint32_t td = dstCur; dstCur = dstNxt; dstNxt = td;
        const char* tp = pCur; pCur = pNxt; pNxt = tp;
        int tph = phCur; phCur = phNxt; phNxt = tph;
    }

    // --- epilogue ---
    if (tid < rows) {
        const int sample = base + tid;
        #pragma unroll
        for (int k = 0; k < NCLS; k++) {
            out[(size_t)sample * NCLS + k] = __ldg(init_out + k) + LR * acc[k];
        }
    }
}

extern "C" void kernel_launch(void* const* d_in, const int* in_sizes, int n_in,
                              void* d_out, int out_size)
{
    (void)in_sizes; (void)n_in; (void)out_size;

    const float* x           = (const float*)d_in[0];
    const int*   features    = (const int*)  d_in[1];
    const float* thresholds  = (const float*)d_in[2];
    const float* leaf_values = (const float*)d_in[3];
    const float* init_out    = (const float*)d_in[4];
    float*       out         = (float*)d_out;

    static bool attr_set = false;
    if (!attr_set) {
        cudaFuncSetAttribute(gbt_forest_kernel,
                             cudaFuncAttributeMaxDynamicSharedMemorySize,
                             SMEM_TOTAL);
        attr_set = true;
    }

    gbt_forest_kernel<<<GRID, TPB, SMEM_TOTAL>>>(
        x, features, thresholds, leaf_values, init_out, out);
}

// round 5
// speedup vs baseline: 1.8965x; 1.0936x over previous
#include <cuda_runtime.h>
#include <cstdint>

// Problem constants
#define BATCH      32768
#define NFEAT      128
#define NTREES     4000
#define NINT       63
#define NLEAF      64
#define NCLS       10
#define TREE_DEPTH 6
#define LR         0.1f

// Tiling: one CTA per SM, balanced grid
#define TPB        224                        // 7 warps = 224 samples per CTA
#define GRID       ((BATCH + TPB - 1) / TPB)  // 147 CTAs over 148 SMs

#define CHUNK_STAGES 4
#define CHUNK_TREES  (CHUNK_STAGES * NCLS)    // 40 trees per buffer
#define NCHUNK       (NTREES / CHUNK_TREES)   // 100

#define FEAT_WORDS  (CHUNK_TREES * NINT)      // 2520
#define LEAF_WORDS  (CHUNK_TREES * NLEAF)     // 2560
#define FEAT_BYTES  (FEAT_WORDS * 4)          // 10080
#define LEAF_BYTES  (LEAF_WORDS * 4)          // 10240
#define BUF_BYTES   (2 * FEAT_BYTES + LEAF_BYTES)   // 30400

// x tile: FEATURE-MAJOR, xs[f * TPB + r]. 224 ≡ 0 (mod 32) makes the
// per-lane gather bank = lane id -> conflict-free for any feature.
#define XS_BYTES    (NFEAT * TPB * 4)         // 114688
#define MBAR_OFF    (XS_BYTES + 2 * BUF_BYTES)
#define SMEM_TOTAL  (MBAR_OFF + 16)

extern __shared__ char smem_raw[];

__device__ __forceinline__ uint32_t s2u(const void* p) {
    uint32_t a;
    asm("{ .reg .u64 t; cvta.to.shared.u64 t, %1; cvt.u32.u64 %0, t; }"
        : "=r"(a) : "l"(p));
    return a;
}

__device__ __forceinline__ void mbar_init(uint32_t bar, uint32_t cnt) {
    asm volatile("mbarrier.init.shared.b64 [%0], %1;" :: "r"(bar), "r"(cnt) : "memory");
}

__device__ __forceinline__ void mbar_expect_tx(uint32_t bar, uint32_t bytes) {
    asm volatile("mbarrier.arrive.expect_tx.shared.b64 _, [%0], %1;"
                 :: "r"(bar), "r"(bytes) : "memory");
}

__device__ __forceinline__ void mbar_wait(uint32_t bar, uint32_t parity) {
    uint32_t done;
    asm volatile(
        "{\n\t.reg .pred p;\n\t"
        "mbarrier.try_wait.parity.acquire.cta.shared::cta.b64 p, [%1], %2;\n\t"
        "selp.b32 %0, 1, 0, p;\n\t}"
        : "=r"(done) : "r"(bar), "r"(parity) : "memory");
    while (!done) {
        asm volatile(
            "{\n\t.reg .pred p;\n\t"
            "mbarrier.try_wait.parity.acquire.cta.shared::cta.b64 p, [%1], %2, 0x989680;\n\t"
            "selp.b32 %0, 1, 0, p;\n\t}"
            : "=r"(done) : "r"(bar), "r"(parity) : "memory");
    }
}

__device__ __forceinline__ void bulk_g2s(uint32_t dst, const void* src,
                                         uint32_t bytes, uint32_t bar) {
    asm volatile(
        "cp.async.bulk.shared::cluster.global.mbarrier::complete_tx::bytes "
        "[%0], [%1], %2, [%3];"
        :: "r"(dst), "l"(src), "r"(bytes), "r"(bar) : "memory");
}

__global__ void __launch_bounds__(TPB, 1)
gbt_forest_kernel(const float* __restrict__ x,
                  const int*   __restrict__ features,
                  const float* __restrict__ thresholds,
                  const float* __restrict__ leaf_values,
                  const float* __restrict__ init_out,
                  float*       __restrict__ out)
{
    float* xs = reinterpret_cast<float*>(smem_raw);

    char* buf0 = smem_raw + XS_BYTES;
    char* buf1 = buf0 + BUF_BYTES;
    uint64_t* mbar = reinterpret_cast<uint64_t*>(smem_raw + MBAR_OFF);

    const int tid  = threadIdx.x;
    const int lane = tid & 31;
    const int warp = tid >> 5;
    const int base = blockIdx.x * TPB;
    const int rows = min(TPB, BATCH - base);

    const uint32_t bar0 = s2u(&mbar[0]);
    const uint32_t bar1 = s2u(&mbar[1]);
    const uint32_t dst0 = s2u(buf0);
    const uint32_t dst1 = s2u(buf1);

    // --- init barriers + prefetch chunks 0,1 via bulk-async ---
    if (tid == 0) {
        mbar_init(bar0, 1);
        mbar_init(bar1, 1);
        asm volatile("fence.proxy.async.shared::cta;" ::: "memory");
        mbar_expect_tx(bar0, BUF_BYTES);
        bulk_g2s(dst0,                  features,                 FEAT_BYTES, bar0);
        bulk_g2s(dst0 + FEAT_BYTES,     thresholds,               FEAT_BYTES, bar0);
        bulk_g2s(dst0 + 2 * FEAT_BYTES, leaf_values,              LEAF_BYTES, bar0);
        mbar_expect_tx(bar1, BUF_BYTES);
        bulk_g2s(dst1,                  features   + FEAT_WORDS,  FEAT_BYTES, bar1);
        bulk_g2s(dst1 + FEAT_BYTES,     thresholds + FEAT_WORDS,  FEAT_BYTES, bar1);
        bulk_g2s(dst1 + 2 * FEAT_BYTES, leaf_values + LEAF_WORDS, LEAF_BYTES, bar1);
    }

    // --- stage x tile TRANSPOSED (feature-major). Each lane owns one row;
    //     STS banks are distinct per lane; LDG.128 is uncoalesced (paid once,
    //     ~4us) to buy conflict-free gathers for the whole mainloop. ---
    {
        const int r  = warp * 32 + lane;                 // 0..223, fixed per thread
        const int gr = min(base + r, BATCH - 1);         // clamp tail CTA
        const float4* xg = reinterpret_cast<const float4*>(x + (size_t)gr * NFEAT);
        #pragma unroll 8
        for (int fq = 0; fq < NFEAT / 4; fq++) {
            float4 v = xg[fq];
            xs[(fq * 4 + 0) * TPB + r] = v.x;
            xs[(fq * 4 + 1) * TPB + r] = v.y;
            xs[(fq * 4 + 2) * TPB + r] = v.z;
            xs[(fq * 4 + 3) * TPB + r] = v.w;
        }
    }
    __syncthreads();

    float acc[NCLS];
    #pragma unroll
    for (int k = 0; k < NCLS; k++) acc[k] = 0.0f;

    const float* xcol = xs + tid;   // gather: xcol[f * TPB], bank == lane

    uint32_t barCur = bar0, barNxt = bar1;
    uint32_t dstCur = dst0, dstNxt = dst1;
    const char* pCur = buf0;
    const char* pNxt = buf1;
    int phCur = 0, phNxt = 0;

    for (int c = 0; c < NCHUNK; c++) {
        mbar_wait(barCur, phCur);
        phCur ^= 1;

        const int*   featB = reinterpret_cast<const int*>(pCur);
        const float* thrB  = reinterpret_cast<const float*>(pCur + FEAT_BYTES);
        const float* leafB = reinterpret_cast<const float*>(pCur + 2 * FEAT_BYTES);

        for (int sg = 0; sg < CHUNK_STAGES; sg++) {
            #pragma unroll
            for (int k = 0; k < NCLS; k++) {
                const int j = sg * NCLS + k;
                const int*   ft = featB + j * NINT;
                const float* tt = thrB  + j * NINT;
                int idx = 0;
                #pragma unroll
                for (int l = 0; l < TREE_DEPTH; l++) {
                    int   f   = ft[idx];              // 1 wf (consecutive range)
                    float thr = tt[idx];              // 1 wf
                    float xv  = xcol[f * TPB];        // 1 wf (conflict-free)
                    idx = 2 * idx + 1 + (xv > thr);
                }
                acc[k] += leafB[j * NLEAF + (idx - NINT)];
            }
        }

        __syncthreads();   // all warps done before buffer overwrite
        if (c + 2 < NCHUNK && tid == 0) {
            const int nc = c + 2;
            mbar_expect_tx(barCur, BUF_BYTES);
            bulk_g2s(dstCur,                  features    + (size_t)nc * FEAT_WORDS, FEAT_BYTES, barCur);
            bulk_g2s(dstCur + FEAT_BYTES,     thresholds  + (size_t)nc * FEAT_WORDS, FEAT_BYTES, barCur);
            bulk_g2s(dstCur + 2 * FEAT_BYTES, leaf_values + (size_t)nc * LEAF_WORDS, LEAF_BYTES, barCur);
        }

        uint32_t tb = barCur; barCur = barNxt; barNxt = tb;
        uint32_t td = dstCur; dstCur = dstNxt; dstNxt = td;
        const char* tp = pCur; pCur = pNxt; pNxt = tp;
        int tph = phCur; phCur = phNxt; phNxt = tph;
    }

    // --- epilogue ---
    if (tid < rows) {
        const int sample = base + tid;
        #pragma unroll
        for (int k = 0; k < NCLS; k++) {
            out[(size_t)sample * NCLS + k] = __ldg(init_out + k) + LR * acc[k];
        }
    }
}

extern "C" void kernel_launch(void* const* d_in, const int* in_sizes, int n_in,
                              void* d_out, int out_size)
{
    (void)in_sizes; (void)n_in; (void)out_size;

    const float* x           = (const float*)d_in[0];
    const int*   features    = (const int*)  d_in[1];
    const float* thresholds  = (const float*)d_in[2];
    const float* leaf_values = (const float*)d_in[3];
    const float* init_out    = (const float*)d_in[4];
    float*       out         = (float*)d_out;

    static bool attr_set = false;
    if (!attr_set) {
        cudaFuncSetAttribute(gbt_forest_kernel,
                             cudaFuncAttributeMaxDynamicSharedMemorySize,
                             SMEM_TOTAL);
        attr_set = true;
    }

    gbt_forest_kernel<<<GRID, TPB, SMEM_TOTAL>>>(
        x, features, thresholds, leaf_values, init_out, out);
}